// round 11
// baseline (speedup 1.0000x reference)
#include <cuda_runtime.h>
#include <cuda_fp16.h>
#include <cstdint>

#define NN 4096
#define II 512
#define HH 2048
#define OO 512
#define NG 8        // groups of 64 input / 64 output cols
#define NHC 8       // h chunks of 256
#define HCW 256

// device scratch
__device__ __half d_xh[(size_t)NN * II];
__device__ __half d_W1h[(size_t)II * HH];
__device__ __half d_W2h[(size_t)HH * OO];
__device__ __half d_Ph[(size_t)NHC * NN * OO];   // split-K partials [hc][n][o], fp16

// ---------------- helpers ----------------
__device__ __forceinline__ void mma_f16(float c[4],
                                        uint32_t a0, uint32_t a1, uint32_t a2, uint32_t a3,
                                        uint32_t b0, uint32_t b1) {
    asm volatile(
        "mma.sync.aligned.m16n8k16.row.col.f32.f16.f16.f32 "
        "{%0,%1,%2,%3}, {%4,%5,%6,%7}, {%8,%9}, {%0,%1,%2,%3};"
        : "+f"(c[0]), "+f"(c[1]), "+f"(c[2]), "+f"(c[3])
        : "r"(a0), "r"(a1), "r"(a2), "r"(a3), "r"(b0), "r"(b1));
}
__device__ __forceinline__ void ldsm4(uint32_t& r0, uint32_t& r1, uint32_t& r2, uint32_t& r3,
                                      uint32_t addr) {
    asm volatile("ldmatrix.sync.aligned.m8n8.x4.shared.b16 {%0,%1,%2,%3}, [%4];"
                 : "=r"(r0), "=r"(r1), "=r"(r2), "=r"(r3) : "r"(addr));
}
__device__ __forceinline__ void ldsm4t(uint32_t& r0, uint32_t& r1, uint32_t& r2, uint32_t& r3,
                                       uint32_t addr) {
    asm volatile("ldmatrix.sync.aligned.m8n8.x4.trans.shared.b16 {%0,%1,%2,%3}, [%4];"
                 : "=r"(r0), "=r"(r1), "=r"(r2), "=r"(r3) : "r"(addr));
}
__device__ __forceinline__ uint32_t smem_u32(const void* p) {
    uint32_t a;
    asm("{ .reg .u64 t; cvta.to.shared.u64 t, %1; cvt.u32.u64 %0, t; }" : "=r"(a) : "l"(p));
    return a;
}
__device__ __forceinline__ uint32_t pack_h2(float a, float b) {
    __half2 h = __floats2half2_rn(a, b);
    return *reinterpret_cast<uint32_t*>(&h);
}
#define CP16(dst, src) \
    asm volatile("cp.async.cg.shared.global [%0], [%1], 16;" :: "r"(dst), "l"(src) : "memory")
#define CP_COMMIT() asm volatile("cp.async.commit_group;" ::: "memory")
#define CP_WAIT(n)  asm volatile("cp.async.wait_group %0;" :: "n"(n) : "memory")

// ---------------- f32 -> f16 prep ----------------
__global__ __launch_bounds__(256) void conv_x(const float* __restrict__ s) {
    size_t i = (size_t)blockIdx.x * 256 + threadIdx.x;
    float4 v = ((const float4*)s)[i];
    ((uint2*)d_xh)[i] = make_uint2(pack_h2(v.x, v.y), pack_h2(v.z, v.w));
}
__global__ __launch_bounds__(256) void conv_w1(const float* __restrict__ s) {
    size_t i = (size_t)blockIdx.x * 256 + threadIdx.x;
    float4 v = ((const float4*)s)[i];
    ((uint2*)d_W1h)[i] = make_uint2(pack_h2(v.x, v.y), pack_h2(v.z, v.w));
}
__global__ __launch_bounds__(256) void conv_w2(const float* __restrict__ s) {
    size_t i = (size_t)blockIdx.x * 256 + threadIdx.x;
    float4 v = ((const float4*)s)[i];
    ((uint2*)d_W2h)[i] = make_uint2(pack_h2(v.x, v.y), pack_h2(v.z, v.w));
}

// ---------------- smem layout (byte offsets; pitches in halves) ----------------
// x  tile [m=64 ][k=64 ] pitch 72  (144B rows; mod128=16 -> ldmatrix conflict-free)
// W1 tile [k=64 ][n=256] pitch 264 (528B; mod128=16)
// W2 tile [k=256][n=64 ] pitch 72
// A2 tile [m=64 ][k=256] pitch 264
#define PA   72
#define PW1  264
#define PW2  72
#define PA2  264
#define HB_X   0
#define HB_W1  9216                    // 64*144
#define HB_W2  43008                   // + 64*528
#define HB_A2  79872                   // + 256*144
#define HB_B1  113664                  // + 64*528
#define SM_TOTAL (HB_B1 + HCW * 4)     // 114688 -> 2 CTAs/SM

// commit group A: x + W1 (consumed by MMA1)
__device__ __forceinline__ void stage_xw1(uint32_t sb, int tid, int rm, int g, int hc) {
    #pragma unroll
    for (int i = 0; i < 2; i++) {                     // x: 64x64 h
        int t = tid + i * 256;
        int r = t >> 3, c = t & 7;
        CP16(sb + HB_X + r * 144 + c * 16,
             d_xh + (size_t)(rm * 64 + r) * II + g * 64 + c * 8);
    }
    #pragma unroll
    for (int i = 0; i < 8; i++) {                     // W1: 64x256 h
        int t = tid + i * 256;
        int k = t >> 5, c = t & 31;
        CP16(sb + HB_W1 + k * 528 + c * 16,
             d_W1h + (size_t)(g * 64 + k) * HH + hc * HCW + c * 8);
    }
    CP_COMMIT();
}
// commit group B: W2 (consumed by MMA2 only -> overlaps MMA1 + relu)
__device__ __forceinline__ void stage_w2(uint32_t sb, int tid, int g, int hc) {
    #pragma unroll
    for (int i = 0; i < 8; i++) {                     // W2: 256x64 h
        int t = tid + i * 256;
        int k = t >> 3, c = t & 7;
        CP16(sb + HB_W2 + k * 144 + c * 16,
             d_W2h + (size_t)(hc * HCW + k) * OO + g * 64 + c * 8);
    }
    CP_COMMIT();
}

__global__ __launch_bounds__(256, 2) void fused_kernel(const float* __restrict__ b1)
{
    extern __shared__ char smraw[];
    float* b1s = reinterpret_cast<float*>(smraw + HB_B1);
    const uint32_t sb = smem_u32(smraw);

    const int tid  = threadIdx.x;
    const int wid  = tid >> 5;
    const int lane = tid & 31;
    const int gq   = lane >> 2;
    const int tq   = lane & 3;
    const int wm   = wid >> 2;      // 0..1 : 32 M-rows each
    const int wn   = wid & 3;       // 0..3 : 64 H-cols (MMA1) / 16 O-cols (MMA2)
    const int hc   = blockIdx.x;    // 0..7
    const int rm   = blockIdx.y;    // 0..63

    const int lrow = (lane & 7) + ((lane >> 3) & 1) * 8;
    const int lk8  = (lane >> 4) << 3;

    if (tid < 64) {
        float4 v = *(const float4*)(b1 + hc * HCW + tid * 4);
        *(float4*)(b1s + tid * 4) = v;
    }

    // Z accumulators persist across all 8 groups: warp tile 32(m) x 64(h)
    float zacc[2][8][4];
    #pragma unroll
    for (int mi = 0; mi < 2; mi++)
        #pragma unroll
        for (int ni = 0; ni < 8; ni++)
            #pragma unroll
            for (int j = 0; j < 4; j++)
                zacc[mi][ni][j] = 0.0f;

    // prologue: stage group 0 (A then B)
    stage_xw1(sb, tid, rm, 0, hc);
    stage_w2(sb, tid, 0, hc);

    for (int g = 0; g < NG; g++) {
        // ---- x/W1 ready; W2 group may still be in flight ----
        CP_WAIT(1);
        __syncthreads();

        // ---- MMA1: Z += x_g @ W1_g  (warp 32x64, K=64) ----
        #pragma unroll
        for (int ks = 0; ks < 4; ks++) {
            const int k0 = ks * 16;
            uint32_t a[2][4];
            #pragma unroll
            for (int mi = 0; mi < 2; mi++)
                ldsm4(a[mi][0], a[mi][1], a[mi][2], a[mi][3],
                      sb + HB_X + (uint32_t)((wm * 32 + mi * 16 + lrow) * PA + k0 + lk8) * 2);
            #pragma unroll
            for (int np = 0; np < 4; np++) {
                int kk = k0 + lrow;
                int nn = wn * 64 + np * 16 + lk8;
                uint32_t b0, b1r, b2, b3;
                ldsm4t(b0, b1r, b2, b3, sb + HB_W1 + (uint32_t)(kk * PW1 + nn) * 2);
                #pragma unroll
                for (int mi = 0; mi < 2; mi++) {
                    mma_f16(zacc[mi][np * 2],     a[mi][0], a[mi][1], a[mi][2], a[mi][3], b0, b1r);
                    mma_f16(zacc[mi][np * 2 + 1], a[mi][0], a[mi][1], a[mi][2], a[mi][3], b2, b3);
                }
            }
        }

        // ---- relu(Z + b1) -> A2 (half) ----
        #pragma unroll
        for (int mi = 0; mi < 2; mi++) {
            const int r0 = wm * 32 + mi * 16 + gq;
            #pragma unroll
            for (int ni = 0; ni < 8; ni++) {
                const int c = wn * 64 + ni * 8 + 2 * tq;
                const float bb0 = b1s[c], bb1 = b1s[c + 1];
                uint32_t h0 = pack_h2(fmaxf(zacc[mi][ni][0] + bb0, 0.f),
                                      fmaxf(zacc[mi][ni][1] + bb1, 0.f));
                uint32_t h1 = pack_h2(fmaxf(zacc[mi][ni][2] + bb0, 0.f),
                                      fmaxf(zacc[mi][ni][3] + bb1, 0.f));
                *(uint32_t*)(smraw + HB_A2 + (uint32_t)((r0)     * PA2 + c) * 2) = h0;
                *(uint32_t*)(smraw + HB_A2 + (uint32_t)((r0 + 8) * PA2 + c) * 2) = h1;
            }
        }
        // W2 drained here (overlapped with MMA1 + relu); full sync makes W2 copies
        // from all threads visible and publishes A2.
        CP_WAIT(0);
        __syncthreads();

        // ---- MMA2: out_g = relu @ W2_g  (warp 32x16, K=256) ----
        float oacc[2][2][4];
        #pragma unroll
        for (int mi = 0; mi < 2; mi++)
            #pragma unroll
            for (int ni = 0; ni < 2; ni++)
                #pragma unroll
                for (int j = 0; j < 4; j++)
                    oacc[mi][ni][j] = 0.0f;

        #pragma unroll
        for (int ks = 0; ks < 16; ks++) {
            const int k0 = ks * 16;
            uint32_t a[2][4];
            #pragma unroll
            for (int mi = 0; mi < 2; mi++)
                ldsm4(a[mi][0], a[mi][1], a[mi][2], a[mi][3],
                      sb + HB_A2 + (uint32_t)((wm * 32 + mi * 16 + lrow) * PA2 + k0 + lk8) * 2);
            int kk = k0 + lrow;
            int nn = wn * 16 + lk8;
            uint32_t b0, b1r, b2, b3;
            ldsm4t(b0, b1r, b2, b3, sb + HB_W2 + (uint32_t)(kk * PW2 + nn) * 2);
            #pragma unroll
            for (int mi = 0; mi < 2; mi++) {
                mma_f16(oacc[mi][0], a[mi][0], a[mi][1], a[mi][2], a[mi][3], b0, b1r);
                mma_f16(oacc[mi][1], a[mi][0], a[mi][1], a[mi][2], a[mi][3], b2, b3);
            }
        }
        __syncthreads();   // all tile reads done -> buffers free

        // ---- restage next group BEFORE the epilogue (overlap with STGs) ----
        if (g < NG - 1) {
            stage_xw1(sb, tid, rm, g + 1, hc);
            stage_w2(sb, tid, g + 1, hc);
        }

        // ---- epilogue: fp16 partial -> d_Ph[hc][n][g*64 + c] ----
        #pragma unroll
        for (int mi = 0; mi < 2; mi++) {
            const size_t n0 = (size_t)rm * 64 + wm * 32 + mi * 16 + gq;
            __half* p0 = d_Ph + ((size_t)hc * NN + n0) * OO + g * 64;
            __half* p1 = p0 + 8 * OO;
            #pragma unroll
            for (int ni = 0; ni < 2; ni++) {
                const int c = wn * 16 + ni * 8 + 2 * tq;
                *(uint32_t*)(p0 + c) = pack_h2(oacc[mi][ni][0], oacc[mi][ni][1]);
                *(uint32_t*)(p1 + c) = pack_h2(oacc[mi][ni][2], oacc[mi][ni][3]);
            }
        }
    }
}

// out[n][o] = b2[o] + sum_hc d_Ph[hc][n][o]
__global__ __launch_bounds__(256) void reduce_kernel(const float* __restrict__ b2,
                                                     float* __restrict__ out)
{
    const size_t idx = (size_t)blockIdx.x * 256 + threadIdx.x;   // 4-elem chunk index
    const int oq = (int)(idx & (OO / 4 - 1)) * 4;
    float4 acc = *(const float4*)(b2 + oq);
    #pragma unroll
    for (int hcb = 0; hcb < NHC; hcb++) {
        uint2 pv = *(const uint2*)((const __half*)d_Ph + (size_t)hcb * NN * OO + idx * 4);
        float2 lo = __half22float2(*reinterpret_cast<__half2*>(&pv.x));
        float2 hi = __half22float2(*reinterpret_cast<__half2*>(&pv.y));
        acc.x += lo.x; acc.y += lo.y; acc.z += hi.x; acc.w += hi.y;
    }
    *(float4*)(out + idx * 4) = acc;
}

extern "C" void kernel_launch(void* const* d_in, const int* in_sizes, int n_in,
                              void* d_out, int out_size)
{
    const float* x  = (const float*)d_in[0];
    const float* W1 = (const float*)d_in[1];
    const float* b1 = (const float*)d_in[2];
    const float* W2 = (const float*)d_in[3];
    const float* b2 = (const float*)d_in[4];
    float* out = (float*)d_out;

    cudaFuncSetAttribute(fused_kernel, cudaFuncAttributeMaxDynamicSharedMemorySize, SM_TOTAL);

    conv_x<<<(NN * II / 4) / 256, 256>>>(x);
    conv_w1<<<(II * HH / 4) / 256, 256>>>(W1);
    conv_w2<<<(HH * OO / 4) / 256, 256>>>(W2);
    fused_kernel<<<dim3(NHC, NN / 64), 256, SM_TOTAL>>>(b1);
    reduce_kernel<<<(NN * OO / 4) / 256, 256>>>(b2, out);
}

// round 12
// speedup vs baseline: 1.2993x; 1.2993x over previous
#include <cuda_runtime.h>
#include <cuda_fp16.h>
#include <cstdint>

#define NN 4096
#define II 512
#define HH 2048
#define OO 512
#define NG 8        // groups of 64 input / 64 output cols
#define NHC 16      // h chunks of 128
#define HCW 128

// device scratch
__device__ __half d_xh[(size_t)NN * II];
__device__ __half d_W1h[(size_t)II * HH];
__device__ __half d_W2h[(size_t)HH * OO];
__device__ __half d_Ph[(size_t)NHC * NN * OO];   // split-K partials [hc][n][o], fp16

// ---------------- helpers ----------------
__device__ __forceinline__ void mma_f16(float c[4],
                                        uint32_t a0, uint32_t a1, uint32_t a2, uint32_t a3,
                                        uint32_t b0, uint32_t b1) {
    asm volatile(
        "mma.sync.aligned.m16n8k16.row.col.f32.f16.f16.f32 "
        "{%0,%1,%2,%3}, {%4,%5,%6,%7}, {%8,%9}, {%0,%1,%2,%3};"
        : "+f"(c[0]), "+f"(c[1]), "+f"(c[2]), "+f"(c[3])
        : "r"(a0), "r"(a1), "r"(a2), "r"(a3), "r"(b0), "r"(b1));
}
__device__ __forceinline__ void ldsm4(uint32_t& r0, uint32_t& r1, uint32_t& r2, uint32_t& r3,
                                      uint32_t addr) {
    asm volatile("ldmatrix.sync.aligned.m8n8.x4.shared.b16 {%0,%1,%2,%3}, [%4];"
                 : "=r"(r0), "=r"(r1), "=r"(r2), "=r"(r3) : "r"(addr));
}
__device__ __forceinline__ void ldsm4t(uint32_t& r0, uint32_t& r1, uint32_t& r2, uint32_t& r3,
                                       uint32_t addr) {
    asm volatile("ldmatrix.sync.aligned.m8n8.x4.trans.shared.b16 {%0,%1,%2,%3}, [%4];"
                 : "=r"(r0), "=r"(r1), "=r"(r2), "=r"(r3) : "r"(addr));
}
__device__ __forceinline__ uint32_t smem_u32(const void* p) {
    uint32_t a;
    asm("{ .reg .u64 t; cvta.to.shared.u64 t, %1; cvt.u32.u64 %0, t; }" : "=r"(a) : "l"(p));
    return a;
}
__device__ __forceinline__ uint32_t pack_h2(float a, float b) {
    __half2 h = __floats2half2_rn(a, b);
    return *reinterpret_cast<uint32_t*>(&h);
}
#define CP16(dst, src) \
    asm volatile("cp.async.cg.shared.global [%0], [%1], 16;" :: "r"(dst), "l"(src) : "memory")
#define CP_COMMIT() asm volatile("cp.async.commit_group;" ::: "memory")
#define CP_WAIT0()  asm volatile("cp.async.wait_group 0;" ::: "memory")
#define BAR_HALF(id) asm volatile("bar.sync %0, 128;" :: "r"(id) : "memory")

// ---------------- f32 -> f16 prep ----------------
__global__ __launch_bounds__(256) void conv_x(const float* __restrict__ s) {
    size_t i = (size_t)blockIdx.x * 256 + threadIdx.x;
    float4 v = ((const float4*)s)[i];
    ((uint2*)d_xh)[i] = make_uint2(pack_h2(v.x, v.y), pack_h2(v.z, v.w));
}
__global__ __launch_bounds__(256) void conv_w1(const float* __restrict__ s) {
    size_t i = (size_t)blockIdx.x * 256 + threadIdx.x;
    float4 v = ((const float4*)s)[i];
    ((uint2*)d_W1h)[i] = make_uint2(pack_h2(v.x, v.y), pack_h2(v.z, v.w));
}
__global__ __launch_bounds__(256) void conv_w2(const float* __restrict__ s) {
    size_t i = (size_t)blockIdx.x * 256 + threadIdx.x;
    float4 v = ((const float4*)s)[i];
    ((uint2*)d_W2h)[i] = make_uint2(pack_h2(v.x, v.y), pack_h2(v.z, v.w));
}

// ---------------- smem layout (byte offsets; pitches in halves) ----------------
// x  tile [m=64 ][k=64 ]  pitch 72  (144B rows; mod128=16 -> ldmatrix conflict-free)
// W1 tile [k=64 ][n=128]  pitch 136 (272B; mod128=16)
// W2 tile [k=128][n=64 ]  pitch 72  (144B)
// A2 tile [m=64 ][k=128]  pitch 136 (272B)
#define PA   72
#define PW1  136
#define PW2  72
#define PA2  136
#define HB_X   0
#define HB_W1  9216                    // + 64*144
#define HB_W2  26624                   // + 64*272
#define HB_A2  45056                   // + 128*144
#define HB_B1  62464                   // + 64*272
#define SM_TOTAL (HB_B1 + HCW * 4)     // 62976 -> 3 CTAs/SM (188928 <= 228KB)

__global__ __launch_bounds__(256, 3) void fused_kernel(const float* __restrict__ b1)
{
    extern __shared__ char smraw[];
    float* b1s = reinterpret_cast<float*>(smraw + HB_B1);
    const uint32_t sb = smem_u32(smraw);

    const int tid  = threadIdx.x;
    const int wid  = tid >> 5;
    const int lane = tid & 31;
    const int gq   = lane >> 2;
    const int tq   = lane & 3;
    const int wm   = wid >> 2;      // 0..1 : 32 M-rows each (tids 0-127 / 128-255)
    const int wn   = wid & 3;       // 0..3 : 32 H-cols (MMA1) / 16 O-cols (MMA2)
    const int hc   = blockIdx.x;    // 0..15
    const int rm   = blockIdx.y;    // 0..63

    const int lrow = (lane & 7) + ((lane >> 3) & 1) * 8;
    const int lk8  = (lane >> 4) << 3;

    if (tid < 32) {
        float4 v = *(const float4*)(b1 + hc * HCW + tid * 4);
        *(float4*)(b1s + tid * 4) = v;
    }

    // Z accumulators persist across all 8 groups: warp tile 32(m) x 32(h)
    float zacc[2][4][4];
    #pragma unroll
    for (int mi = 0; mi < 2; mi++)
        #pragma unroll
        for (int ni = 0; ni < 4; ni++)
            #pragma unroll
            for (int j = 0; j < 4; j++)
                zacc[mi][ni][j] = 0.0f;

    for (int g = 0; g < NG; g++) {
        // ---- stage all three tiles via cp.async (R8 schedule) ----
        #pragma unroll
        for (int i = 0; i < 2; i++) {                     // x: 64x64 h
            int t = tid + i * 256;
            int r = t >> 3, c = t & 7;
            CP16(sb + HB_X + r * 144 + c * 16,
                 d_xh + (size_t)(rm * 64 + r) * II + g * 64 + c * 8);
        }
        #pragma unroll
        for (int i = 0; i < 4; i++) {                     // W1: 64x128 h
            int t = tid + i * 256;
            int k = t >> 4, c = t & 15;
            CP16(sb + HB_W1 + k * 272 + c * 16,
                 d_W1h + (size_t)(g * 64 + k) * HH + hc * HCW + c * 8);
        }
        #pragma unroll
        for (int i = 0; i < 4; i++) {                     // W2: 128x64 h
            int t = tid + i * 256;
            int k = t >> 3, c = t & 7;
            CP16(sb + HB_W2 + k * 144 + c * 16,
                 d_W2h + (size_t)(hc * HCW + k) * OO + g * 64 + c * 8);
        }
        CP_COMMIT();
        CP_WAIT0();
        __syncthreads();

        // ---- MMA1: Z += x_g @ W1_g  (warp 32x32, K=64) ----
        #pragma unroll
        for (int ks = 0; ks < 4; ks++) {
            const int k0 = ks * 16;
            uint32_t a[2][4];
            #pragma unroll
            for (int mi = 0; mi < 2; mi++)
                ldsm4(a[mi][0], a[mi][1], a[mi][2], a[mi][3],
                      sb + HB_X + (uint32_t)((wm * 32 + mi * 16 + lrow) * PA + k0 + lk8) * 2);
            #pragma unroll
            for (int np = 0; np < 2; np++) {
                int kk = k0 + lrow;
                int nn = wn * 32 + np * 16 + lk8;
                uint32_t b0, b1r, b2, b3;
                ldsm4t(b0, b1r, b2, b3, sb + HB_W1 + (uint32_t)(kk * PW1 + nn) * 2);
                #pragma unroll
                for (int mi = 0; mi < 2; mi++) {
                    mma_f16(zacc[mi][np * 2],     a[mi][0], a[mi][1], a[mi][2], a[mi][3], b0, b1r);
                    mma_f16(zacc[mi][np * 2 + 1], a[mi][0], a[mi][1], a[mi][2], a[mi][3], b2, b3);
                }
            }
        }

        // ---- relu(Z + b1) -> A2 (half) ----
        #pragma unroll
        for (int mi = 0; mi < 2; mi++) {
            const int r0 = wm * 32 + mi * 16 + gq;
            #pragma unroll
            for (int ni = 0; ni < 4; ni++) {
                const int c = wn * 32 + ni * 8 + 2 * tq;
                const float bb0 = b1s[c], bb1 = b1s[c + 1];
                uint32_t h0 = pack_h2(fmaxf(zacc[mi][ni][0] + bb0, 0.f),
                                      fmaxf(zacc[mi][ni][1] + bb1, 0.f));
                uint32_t h1 = pack_h2(fmaxf(zacc[mi][ni][2] + bb0, 0.f),
                                      fmaxf(zacc[mi][ni][3] + bb1, 0.f));
                *(uint32_t*)(smraw + HB_A2 + (uint32_t)((r0)     * PA2 + c) * 2) = h0;
                *(uint32_t*)(smraw + HB_A2 + (uint32_t)((r0 + 8) * PA2 + c) * 2) = h1;
            }
        }
        // MMA2's A rows for this wm-half are written only by this wm-half's 4 warps
        BAR_HALF(1 + wm);

        // ---- MMA2: out_g = relu @ W2_g  (warp 32x16, K=128) ----
        float oacc[2][2][4];
        #pragma unroll
        for (int mi = 0; mi < 2; mi++)
            #pragma unroll
            for (int ni = 0; ni < 2; ni++)
                #pragma unroll
                for (int j = 0; j < 4; j++)
                    oacc[mi][ni][j] = 0.0f;

        #pragma unroll
        for (int ks = 0; ks < 8; ks++) {
            const int k0 = ks * 16;
            uint32_t a[2][4];
            #pragma unroll
            for (int mi = 0; mi < 2; mi++)
                ldsm4(a[mi][0], a[mi][1], a[mi][2], a[mi][3],
                      sb + HB_A2 + (uint32_t)((wm * 32 + mi * 16 + lrow) * PA2 + k0 + lk8) * 2);
            int kk = k0 + lrow;
            int nn = wn * 16 + lk8;
            uint32_t b0, b1r, b2, b3;
            ldsm4t(b0, b1r, b2, b3, sb + HB_W2 + (uint32_t)(kk * PW2 + nn) * 2);
            #pragma unroll
            for (int mi = 0; mi < 2; mi++) {
                mma_f16(oacc[mi][0], a[mi][0], a[mi][1], a[mi][2], a[mi][3], b0, b1r);
                mma_f16(oacc[mi][1], a[mi][0], a[mi][1], a[mi][2], a[mi][3], b2, b3);
            }
        }
        __syncthreads();   // all smem reads done before next group's staging

        // ---- epilogue: fp16 partial -> d_Ph[hc][n][g*64 + c] ----
        #pragma unroll
        for (int mi = 0; mi < 2; mi++) {
            const size_t n0 = (size_t)rm * 64 + wm * 32 + mi * 16 + gq;
            __half* p0 = d_Ph + ((size_t)hc * NN + n0) * OO + g * 64;
            __half* p1 = p0 + 8 * OO;
            #pragma unroll
            for (int ni = 0; ni < 2; ni++) {
                const int c = wn * 16 + ni * 8 + 2 * tq;
                *(uint32_t*)(p0 + c) = pack_h2(oacc[mi][ni][0], oacc[mi][ni][1]);
                *(uint32_t*)(p1 + c) = pack_h2(oacc[mi][ni][2], oacc[mi][ni][3]);
            }
        }
    }
}

// out[n][o] = b2[o] + sum_hc d_Ph[hc][n][o]
__global__ __launch_bounds__(256) void reduce_kernel(const float* __restrict__ b2,
                                                     float* __restrict__ out)
{
    const size_t idx = (size_t)blockIdx.x * 256 + threadIdx.x;   // 4-elem chunk index
    const int oq = (int)(idx & (OO / 4 - 1)) * 4;
    float4 acc = *(const float4*)(b2 + oq);
    #pragma unroll
    for (int hcb = 0; hcb < NHC; hcb++) {
        uint2 pv = *(const uint2*)((const __half*)d_Ph + (size_t)hcb * NN * OO + idx * 4);
        float2 lo = __half22float2(*reinterpret_cast<__half2*>(&pv.x));
        float2 hi = __half22float2(*reinterpret_cast<__half2*>(&pv.y));
        acc.x += lo.x; acc.y += lo.y; acc.z += hi.x; acc.w += hi.y;
    }
    *(float4*)(out + idx * 4) = acc;
}

extern "C" void kernel_launch(void* const* d_in, const int* in_sizes, int n_in,
                              void* d_out, int out_size)
{
    const float* x  = (const float*)d_in[0];
    const float* W1 = (const float*)d_in[1];
    const float* b1 = (const float*)d_in[2];
    const float* W2 = (const float*)d_in[3];
    const float* b2 = (const float*)d_in[4];
    float* out = (float*)d_out;

    cudaFuncSetAttribute(fused_kernel, cudaFuncAttributeMaxDynamicSharedMemorySize, SM_TOTAL);

    conv_x<<<(NN * II / 4) / 256, 256>>>(x);
    conv_w1<<<(II * HH / 4) / 256, 256>>>(W1);
    conv_w2<<<(HH * OO / 4) / 256, 256>>>(W2);
    fused_kernel<<<dim3(NHC, NN / 64), 256, SM_TOTAL>>>(b1);
    reduce_kernel<<<(NN * OO / 4) / 256, 256>>>(b2, out);
}

// round 13
// speedup vs baseline: 1.4882x; 1.1454x over previous
#include <cuda_runtime.h>
#include <cuda_fp16.h>
#include <cstdint>

#define NN 4096
#define II 512
#define HH 2048
#define OO 512
#define NG 8        // groups of 64 input / 64 output cols
#define NHC 8       // h chunks of 256
#define HCW 256

// device scratch
__device__ __half d_xh[(size_t)NN * II];
__device__ __half d_W1h[(size_t)II * HH];
__device__ __half d_W2h[(size_t)HH * OO];
__device__ __half d_Ph[(size_t)NHC * NN * OO];   // split-K partials [hc][n][o], fp16

// ---------------- helpers ----------------
__device__ __forceinline__ void mma_f16(float c[4],
                                        uint32_t a0, uint32_t a1, uint32_t a2, uint32_t a3,
                                        uint32_t b0, uint32_t b1) {
    asm volatile(
        "mma.sync.aligned.m16n8k16.row.col.f32.f16.f16.f32 "
        "{%0,%1,%2,%3}, {%4,%5,%6,%7}, {%8,%9}, {%0,%1,%2,%3};"
        : "+f"(c[0]), "+f"(c[1]), "+f"(c[2]), "+f"(c[3])
        : "r"(a0), "r"(a1), "r"(a2), "r"(a3), "r"(b0), "r"(b1));
}
__device__ __forceinline__ void ldsm4(uint32_t& r0, uint32_t& r1, uint32_t& r2, uint32_t& r3,
                                      uint32_t addr) {
    asm volatile("ldmatrix.sync.aligned.m8n8.x4.shared.b16 {%0,%1,%2,%3}, [%4];"
                 : "=r"(r0), "=r"(r1), "=r"(r2), "=r"(r3) : "r"(addr));
}
__device__ __forceinline__ void ldsm4t(uint32_t& r0, uint32_t& r1, uint32_t& r2, uint32_t& r3,
                                       uint32_t addr) {
    asm volatile("ldmatrix.sync.aligned.m8n8.x4.trans.shared.b16 {%0,%1,%2,%3}, [%4];"
                 : "=r"(r0), "=r"(r1), "=r"(r2), "=r"(r3) : "r"(addr));
}
__device__ __forceinline__ uint32_t smem_u32(const void* p) {
    uint32_t a;
    asm("{ .reg .u64 t; cvta.to.shared.u64 t, %1; cvt.u32.u64 %0, t; }" : "=r"(a) : "l"(p));
    return a;
}
__device__ __forceinline__ uint32_t pack_h2(float a, float b) {
    __half2 h = __floats2half2_rn(a, b);
    return *reinterpret_cast<uint32_t*>(&h);
}
#define CP16(dst, src) \
    asm volatile("cp.async.cg.shared.global [%0], [%1], 16;" :: "r"(dst), "l"(src) : "memory")
#define CP_COMMIT() asm volatile("cp.async.commit_group;" ::: "memory")
#define CP_WAIT0()  asm volatile("cp.async.wait_group 0;" ::: "memory")
#define BAR_HALF(id) asm volatile("bar.sync %0, 128;" :: "r"(id) : "memory")
#define STS32(addr, v) \
    asm volatile("st.shared.b32 [%0], %1;" :: "r"(addr), "r"(v) : "memory")

// XOR-swizzled address: power-of-2 row pitch, 16B segment ^= (row & 7)
__device__ __forceinline__ uint32_t swz(uint32_t base, int row, int seg, int pitch) {
    return base + (uint32_t)(row * pitch) + (uint32_t)(((seg ^ (row & 7)) << 4));
}

// ---------------- f32 -> f16 prep ----------------
__global__ __launch_bounds__(256) void conv_x(const float* __restrict__ s) {
    size_t i = (size_t)blockIdx.x * 256 + threadIdx.x;
    float4 v = ((const float4*)s)[i];
    ((uint2*)d_xh)[i] = make_uint2(pack_h2(v.x, v.y), pack_h2(v.z, v.w));
}
__global__ __launch_bounds__(256) void conv_w1(const float* __restrict__ s) {
    size_t i = (size_t)blockIdx.x * 256 + threadIdx.x;
    float4 v = ((const float4*)s)[i];
    ((uint2*)d_W1h)[i] = make_uint2(pack_h2(v.x, v.y), pack_h2(v.z, v.w));
}
__global__ __launch_bounds__(256) void conv_w2(const float* __restrict__ s) {
    size_t i = (size_t)blockIdx.x * 256 + threadIdx.x;
    float4 v = ((const float4*)s)[i];
    ((uint2*)d_W2h)[i] = make_uint2(pack_h2(v.x, v.y), pack_h2(v.z, v.w));
}

// ---------------- smem layout: power-of-2 pitches + XOR swizzle ----------------
// x  tile [m=64 ][k=64 ]  pitch 128B (8 segs)
// W1 tile [k=64 ][n=256]  pitch 512B (32 segs)
// W2 tile [k=256][n=64 ]  pitch 128B (8 segs)
// A2 tile [m=64 ][k=256]  pitch 512B (32 segs)
#define HB_X   0
#define HB_W1  8192                    // + 64*128
#define HB_W2  40960                   // + 64*512
#define HB_A2  73728                   // + 256*128
#define HB_B1  106496                  // + 64*512
#define SM_TOTAL (HB_B1 + HCW * 4)     // 107520 -> 2 CTAs/SM

__global__ __launch_bounds__(256, 2) void fused_kernel(const float* __restrict__ b1)
{
    extern __shared__ char smraw[];
    float* b1s = reinterpret_cast<float*>(smraw + HB_B1);
    const uint32_t sb = smem_u32(smraw);

    const int tid  = threadIdx.x;
    const int wid  = tid >> 5;
    const int lane = tid & 31;
    const int gq   = lane >> 2;
    const int tq   = lane & 3;
    const int wm   = wid >> 2;      // 0..1 : 32 M-rows each (tids 0-127 / 128-255)
    const int wn   = wid & 3;       // 0..3 : 64 H-cols (MMA1) / 16 O-cols (MMA2)
    const int hc   = blockIdx.x;    // 0..7
    const int rm   = blockIdx.y;    // 0..63

    const int lrow = (lane & 7) + ((lane >> 3) & 1) * 8;   // row within 16
    const int lkb  = lane >> 4;                            // 0/1: which 8-col block
    const int lr7  = lrow & 7;

    if (tid < 64) {
        float4 v = *(const float4*)(b1 + hc * HCW + tid * 4);
        *(float4*)(b1s + tid * 4) = v;
    }

    // Z accumulators persist across all 8 groups: warp tile 32(m) x 64(h)
    float zacc[2][8][4];
    #pragma unroll
    for (int mi = 0; mi < 2; mi++)
        #pragma unroll
        for (int ni = 0; ni < 8; ni++)
            #pragma unroll
            for (int j = 0; j < 4; j++)
                zacc[mi][ni][j] = 0.0f;

    for (int g = 0; g < NG; g++) {
        // ---- stage all three tiles via cp.async into swizzled layouts ----
        #pragma unroll
        for (int i = 0; i < 2; i++) {                     // x: 64 rows x 8 segs
            int t = tid + i * 256;
            int r = t >> 3, c = t & 7;
            CP16(swz(sb + HB_X, r, c, 128),
                 d_xh + (size_t)(rm * 64 + r) * II + g * 64 + c * 8);
        }
        #pragma unroll
        for (int i = 0; i < 8; i++) {                     // W1: 64 rows x 32 segs
            int t = tid + i * 256;
            int k = t >> 5, c = t & 31;
            CP16(swz(sb + HB_W1, k, c, 512),
                 d_W1h + (size_t)(g * 64 + k) * HH + hc * HCW + c * 8);
        }
        #pragma unroll
        for (int i = 0; i < 8; i++) {                     // W2: 256 rows x 8 segs
            int t = tid + i * 256;
            int k = t >> 3, c = t & 7;
            CP16(swz(sb + HB_W2, k, c, 128),
                 d_W2h + (size_t)(hc * HCW + k) * OO + g * 64 + c * 8);
        }
        CP_COMMIT();
        CP_WAIT0();
        __syncthreads();

        // ---- MMA1: Z += x_g @ W1_g  (warp 32x64, K=64) ----
        #pragma unroll
        for (int ks = 0; ks < 4; ks++) {
            uint32_t a[2][4];
            #pragma unroll
            for (int mi = 0; mi < 2; mi++)
                ldsm4(a[mi][0], a[mi][1], a[mi][2], a[mi][3],
                      swz(sb + HB_X, wm * 32 + mi * 16 + lrow, ks * 2 + lkb, 128));
            #pragma unroll
            for (int np = 0; np < 4; np++) {
                uint32_t b0, b1r, b2, b3;
                ldsm4t(b0, b1r, b2, b3,
                       swz(sb + HB_W1, ks * 16 + lrow, wn * 8 + np * 2 + lkb, 512));
                #pragma unroll
                for (int mi = 0; mi < 2; mi++) {
                    mma_f16(zacc[mi][np * 2],     a[mi][0], a[mi][1], a[mi][2], a[mi][3], b0, b1r);
                    mma_f16(zacc[mi][np * 2 + 1], a[mi][0], a[mi][1], a[mi][2], a[mi][3], b2, b3);
                }
            }
        }

        // ---- relu(Z + b1) -> A2 (swizzled; conflict-free STS) ----
        #pragma unroll
        for (int mi = 0; mi < 2; mi++) {
            const int r0 = wm * 32 + mi * 16 + gq;        // r0 & 7 == gq
            #pragma unroll
            for (int ni = 0; ni < 8; ni++) {
                const int c = wn * 64 + ni * 8 + 2 * tq;
                const int seg = wn * 8 + ni;
                const float bb0 = b1s[c], bb1 = b1s[c + 1];
                uint32_t h0 = pack_h2(fmaxf(zacc[mi][ni][0] + bb0, 0.f),
                                      fmaxf(zacc[mi][ni][1] + bb1, 0.f));
                uint32_t h1 = pack_h2(fmaxf(zacc[mi][ni][2] + bb0, 0.f),
                                      fmaxf(zacc[mi][ni][3] + bb1, 0.f));
                uint32_t ad = swz(sb + HB_A2, r0, seg, 512) + tq * 4;
                STS32(ad, h0);
                STS32(ad + 8 * 512, h1);
            }
        }
        // MMA2's A rows for this wm-half are written only by this wm-half's 4 warps
        BAR_HALF(1 + wm);

        // ---- MMA2: out_g = relu @ W2_g  (warp 32x16, K=256) ----
        float oacc[2][2][4];
        #pragma unroll
        for (int mi = 0; mi < 2; mi++)
            #pragma unroll
            for (int ni = 0; ni < 2; ni++)
                #pragma unroll
                for (int j = 0; j < 4; j++)
                    oacc[mi][ni][j] = 0.0f;

        #pragma unroll
        for (int ks = 0; ks < 16; ks++) {
            uint32_t a[2][4];
            #pragma unroll
            for (int mi = 0; mi < 2; mi++)
                ldsm4(a[mi][0], a[mi][1], a[mi][2], a[mi][3],
                      swz(sb + HB_A2, wm * 32 + mi * 16 + lrow, ks * 2 + lkb, 512));
            uint32_t b0, b1r, b2, b3;
            ldsm4t(b0, b1r, b2, b3,
                   swz(sb + HB_W2, ks * 16 + lrow, wn * 2 + lkb, 128));
            #pragma unroll
            for (int mi = 0; mi < 2; mi++) {
                mma_f16(oacc[mi][0], a[mi][0], a[mi][1], a[mi][2], a[mi][3], b0, b1r);
                mma_f16(oacc[mi][1], a[mi][0], a[mi][1], a[mi][2], a[mi][3], b2, b3);
            }
        }
        __syncthreads();   // all smem reads done before next group's staging

        // ---- epilogue: fp16 partial -> d_Ph[hc][n][g*64 + c] ----
        #pragma unroll
        for (int mi = 0; mi < 2; mi++) {
            const size_t n0 = (size_t)rm * 64 + wm * 32 + mi * 16 + gq;
            __half* p0 = d_Ph + ((size_t)hc * NN + n0) * OO + g * 64;
            __half* p1 = p0 + 8 * OO;
            #pragma unroll
            for (int ni = 0; ni < 2; ni++) {
                const int c = wn * 16 + ni * 8 + 2 * tq;
                *(uint32_t*)(p0 + c) = pack_h2(oacc[mi][ni][0], oacc[mi][ni][1]);
                *(uint32_t*)(p1 + c) = pack_h2(oacc[mi][ni][2], oacc[mi][ni][3]);
            }
        }
    }
}

// out[n][o] = b2[o] + sum_hc d_Ph[hc][n][o]
__global__ __launch_bounds__(256) void reduce_kernel(const float* __restrict__ b2,
                                                     float* __restrict__ out)
{
    const size_t idx = (size_t)blockIdx.x * 256 + threadIdx.x;   // 4-elem chunk index
    const int oq = (int)(idx & (OO / 4 - 1)) * 4;
    float4 acc = *(const float4*)(b2 + oq);
    #pragma unroll
    for (int hcb = 0; hcb < NHC; hcb++) {
        uint2 pv = *(const uint2*)((const __half*)d_Ph + (size_t)hcb * NN * OO + idx * 4);
        float2 lo = __half22float2(*reinterpret_cast<__half2*>(&pv.x));
        float2 hi = __half22float2(*reinterpret_cast<__half2*>(&pv.y));
        acc.x += lo.x; acc.y += lo.y; acc.z += hi.x; acc.w += hi.y;
    }
    *(float4*)(out + idx * 4) = acc;
}

extern "C" void kernel_launch(void* const* d_in, const int* in_sizes, int n_in,
                              void* d_out, int out_size)
{
    const float* x  = (const float*)d_in[0];
    const float* W1 = (const float*)d_in[1];
    const float* b1 = (const float*)d_in[2];
    const float* W2 = (const float*)d_in[3];
    const float* b2 = (const float*)d_in[4];
    float* out = (float*)d_out;

    cudaFuncSetAttribute(fused_kernel, cudaFuncAttributeMaxDynamicSharedMemorySize, SM_TOTAL);

    conv_x<<<(NN * II / 4) / 256, 256>>>(x);
    conv_w1<<<(II * HH / 4) / 256, 256>>>(W1);
    conv_w2<<<(HH * OO / 4) / 256, 256>>>(W2);
    fused_kernel<<<dim3(NHC, NN / 64), 256, SM_TOTAL>>>(b1);
    reduce_kernel<<<(NN * OO / 4) / 256, 256>>>(b2, out);
}